// round 2
// baseline (speedup 1.0000x reference)
#include <cuda_runtime.h>
#include <cstdint>

#define Nn 131072
#define Ee 262144
#define Dd 128
#define EPS 1e-5f

// ---------------- scratch (no allocation allowed) ----------------
static __device__ float g_h  [(size_t)Nn * Dd];        // raw hm (gemm2 out) / h0
static __device__ float g_agg[(size_t)Nn * Dd];        // aggregation buffer
static __device__ float g_hm1[(size_t)Nn * 2 * Dd];    // gemm1 out
static __device__ float g_stats[2 * Dd];               // col sums / sumsq

// ---------------- h0 = x_emb1[x[:,0]] + x_emb2[x[:,1]] ----------------
__global__ void init_h_kernel(const int* __restrict__ x,
                              const float* __restrict__ emb1,
                              const float* __restrict__ emb2,
                              float* __restrict__ h)
{
    int idx = blockIdx.x * blockDim.x + threadIdx.x;   // Nn * 32 threads
    int n = idx >> 5;
    int j = (idx & 31) * 4;
    int i0 = x[2 * n];
    int i1 = x[2 * n + 1];
    float4 a = *(const float4*)&emb1[(size_t)i0 * Dd + j];
    float4 b = *(const float4*)&emb2[(size_t)i1 * Dd + j];
    float4 o = {a.x + b.x, a.y + b.y, a.z + b.z, a.w + b.w};
    *(float4*)&h[(size_t)n * Dd + j] = o;
}

// Apply previous layer's BatchNorm (+relu) on the fly when reading raw hm.
__device__ __forceinline__ float4 load_h_bn(const float* __restrict__ h,
                                            int node, int j, int apply_bn,
                                            const float* __restrict__ gamma,
                                            const float* __restrict__ beta)
{
    float4 v = *(const float4*)&h[(size_t)node * Dd + j];
    if (apply_bn) {
        const float inv_n = 1.0f / (float)Nn;
#pragma unroll
        for (int t = 0; t < 4; t++) {
            int cc = j + t;
            float mu  = g_stats[cc] * inv_n;
            float var = g_stats[Dd + cc] * inv_n - mu * mu;
            float sc  = rsqrtf(var + EPS) * gamma[cc];
            float sh  = beta[cc] - mu * sc;
            float val = ((const float*)&v)[t] * sc + sh;
            ((float*)&v)[t] = fmaxf(val, 0.f);   // layers 0..3 always relu
        }
    }
    return v;
}

// ---------------- agg init: self-loop message, plain store ----------------
__global__ void agg_init_kernel(const float* __restrict__ h,
                                const float* __restrict__ ee1,  // [6,128]
                                const float* __restrict__ ee2,  // [3,128]
                                float* __restrict__ agg, int apply_bn,
                                const float* __restrict__ gamma,
                                const float* __restrict__ beta)
{
    int idx = blockIdx.x * blockDim.x + threadIdx.x;   // Nn * 32 threads
    int n = idx >> 5;
    int j = (idx & 31) * 4;
    float4 hv = load_h_bn(h, n, j, apply_bn, gamma, beta);
    float4 e1 = *(const float4*)&ee1[(size_t)4 * Dd + j];  // self-loop attr0 = 4
    float4 e2 = *(const float4*)&ee2[j];                   // self-loop attr1 = 0
    float4 o = {hv.x + e1.x + e2.x, hv.y + e1.y + e2.y,
                hv.z + e1.z + e2.z, hv.w + e1.w + e2.w};
    *(float4*)&agg[(size_t)n * Dd + j] = o;
}

// ---------------- edge message + scatter-add (one warp per edge) ----------------
__global__ void scatter_kernel(const float* __restrict__ h,
                               const int* __restrict__ edge_index,
                               const int* __restrict__ edge_attr,
                               const float* __restrict__ ee1,
                               const float* __restrict__ ee2,
                               float* __restrict__ agg, int apply_bn,
                               const float* __restrict__ gamma,
                               const float* __restrict__ beta)
{
    int warp = (blockIdx.x * blockDim.x + threadIdx.x) >> 5;
    int lane = threadIdx.x & 31;
    if (warp >= Ee) return;

    int r  = edge_index[warp];
    int c  = edge_index[Ee + warp];
    int a0 = edge_attr[2 * warp];
    int a1 = edge_attr[2 * warp + 1];

    int j = lane * 4;
    float4 hv = load_h_bn(h, r, j, apply_bn, gamma, beta);
    float4 e1 = *(const float4*)&ee1[(size_t)a0 * Dd + j];
    float4 e2 = *(const float4*)&ee2[(size_t)a1 * Dd + j];
    float4 v = {hv.x + e1.x + e2.x, hv.y + e1.y + e2.y,
                hv.z + e1.z + e2.z, hv.w + e1.w + e2.w};
    float* dst = &agg[(size_t)c * Dd + j];
    asm volatile("red.global.add.v4.f32 [%0], {%1, %2, %3, %4};"
                 :: "l"(dst), "f"(v.x), "f"(v.y), "f"(v.z), "f"(v.w)
                 : "memory");
}

// ---------------- fp32 tiled GEMM: C[M,Nc] = A[M,K] @ B[K,Nc] + bias (+relu) ----------------
template<int BM, int BN, int BK, int TM, int TN, bool RELU>
__global__ __launch_bounds__(256)
void gemm_kernel(const float* __restrict__ A, const float* __restrict__ B,
                 const float* __restrict__ bias, float* __restrict__ C,
                 int M, int Nc, int K)
{
    __shared__ float As[BK][BM];
    __shared__ float Bs[BK][BN];
    const int tid = threadIdx.x;
    const int tx = tid % (BN / TN);        // 16
    const int ty = tid / (BN / TN);        // 16
    const int rb = blockIdx.y * BM;
    const int cb = blockIdx.x * BN;

    const int a_row = tid / (BK / 4);          // 0..127
    const int a_col = (tid % (BK / 4)) * 4;    // 0 or 4
    const int b_row = tid / (BN / 4);          // 0..7
    const int b_col = (tid % (BN / 4)) * 4;    // 0..124

    float acc[TM][TN] = {};

    for (int k0 = 0; k0 < K; k0 += BK) {
        float4 av = *(const float4*)&A[(size_t)(rb + a_row) * K + k0 + a_col];
        As[a_col + 0][a_row] = av.x;
        As[a_col + 1][a_row] = av.y;
        As[a_col + 2][a_row] = av.z;
        As[a_col + 3][a_row] = av.w;
        *(float4*)&Bs[b_row][b_col] =
            *(const float4*)&B[(size_t)(k0 + b_row) * Nc + cb + b_col];
        __syncthreads();
#pragma unroll
        for (int kk = 0; kk < BK; kk++) {
            float af[TM], bf[TN];
#pragma unroll
            for (int i = 0; i < TM; i += 4)
                *(float4*)&af[i] = *(const float4*)&As[kk][ty * TM + i];
#pragma unroll
            for (int j = 0; j < TN; j += 4)
                *(float4*)&bf[j] = *(const float4*)&Bs[kk][tx * TN + j];
#pragma unroll
            for (int i = 0; i < TM; i++)
#pragma unroll
                for (int j = 0; j < TN; j++)
                    acc[i][j] = fmaf(af[i], bf[j], acc[i][j]);
        }
        __syncthreads();
    }

#pragma unroll
    for (int i = 0; i < TM; i++) {
        int r = rb + ty * TM + i;
#pragma unroll
        for (int j = 0; j < TN; j += 4) {
            int c = cb + tx * TN + j;
            float4 o;
            o.x = acc[i][j + 0] + bias[c + 0];
            o.y = acc[i][j + 1] + bias[c + 1];
            o.z = acc[i][j + 2] + bias[c + 2];
            o.w = acc[i][j + 3] + bias[c + 3];
            if (RELU) {
                o.x = fmaxf(o.x, 0.f); o.y = fmaxf(o.y, 0.f);
                o.z = fmaxf(o.z, 0.f); o.w = fmaxf(o.w, 0.f);
            }
            *(float4*)&C[(size_t)r * Nc + c] = o;
        }
    }
}

// ---------------- BatchNorm column stats (sum, sumsq) ----------------
#define BN_ROWS 128
__global__ void bn_stats_kernel(const float* __restrict__ X)
{
    int c = threadIdx.x;                  // 0..127
    size_t r0 = (size_t)blockIdx.x * BN_ROWS;
    float s = 0.f, ss = 0.f;
#pragma unroll 8
    for (int r = 0; r < BN_ROWS; r++) {
        float v = X[(r0 + r) * Dd + c];
        s += v;
        ss += v * v;
    }
    atomicAdd(&g_stats[c], s);
    atomicAdd(&g_stats[Dd + c], ss);
}

// ---------------- final BatchNorm normalize (no relu), layer 4 only ----------------
__global__ void bn_norm_kernel(const float* __restrict__ X, float* __restrict__ Y,
                               const float* __restrict__ gamma,
                               const float* __restrict__ beta)
{
    int idx = blockIdx.x * blockDim.x + threadIdx.x;   // Nn * 32
    int n = idx >> 5;
    int c = (idx & 31) * 4;
    const float inv_n = 1.0f / (float)Nn;
    float4 v = *(const float4*)&X[(size_t)n * Dd + c];
    float4 o;
#pragma unroll
    for (int t = 0; t < 4; t++) {
        int cc = c + t;
        float mu  = g_stats[cc] * inv_n;
        float var = g_stats[Dd + cc] * inv_n - mu * mu;
        float sc = rsqrtf(var + EPS) * gamma[cc];
        float sh = beta[cc] - mu * sc;
        ((float*)&o)[t] = ((const float*)&v)[t] * sc + sh;
    }
    *(float4*)&Y[(size_t)n * Dd + c] = o;
}

// ---------------- driver ----------------
extern "C" void kernel_launch(void* const* d_in, const int* in_sizes, int n_in,
                              void* d_out, int out_size)
{
    const int*   x          = (const int*)  d_in[0];
    const int*   edge_index = (const int*)  d_in[1];
    const int*   edge_attr  = (const int*)  d_in[2];
    const float* x_emb1     = (const float*)d_in[3];
    const float* x_emb2     = (const float*)d_in[4];
    const float* e_emb1     = (const float*)d_in[5];   // [5,6,128]
    const float* e_emb2     = (const float*)d_in[6];   // [5,3,128]
    const float* W1         = (const float*)d_in[7];   // [5,128,256]
    const float* b1         = (const float*)d_in[8];   // [5,256]
    const float* W2         = (const float*)d_in[9];   // [5,256,128]
    const float* b2         = (const float*)d_in[10];  // [5,128]
    const float* gamma      = (const float*)d_in[11];  // [5,128]
    const float* beta       = (const float*)d_in[12];  // [5,128]
    float* out = (float*)d_out;

    float *h, *agg, *hm1, *stats;
    cudaGetSymbolAddress((void**)&h,     g_h);
    cudaGetSymbolAddress((void**)&agg,   g_agg);
    cudaGetSymbolAddress((void**)&hm1,   g_hm1);
    cudaGetSymbolAddress((void**)&stats, g_stats);

    init_h_kernel<<<(Nn * 32) / 256, 256>>>(x, x_emb1, x_emb2, h);

    for (int l = 0; l < 5; l++) {
        const float* ee1 = e_emb1 + (size_t)l * 6 * Dd;
        const float* ee2 = e_emb2 + (size_t)l * 3 * Dd;
        // BN params of PREVIOUS layer (folded into gather), valid only for l>0
        const float* pg = gamma + (size_t)(l > 0 ? l - 1 : 0) * Dd;
        const float* pb = beta  + (size_t)(l > 0 ? l - 1 : 0) * Dd;
        int apply_bn = (l > 0) ? 1 : 0;

        // agg = bn_relu(h) + ee_self  (plain stores; replaces memset)
        agg_init_kernel<<<(Nn * 32) / 256, 256>>>(h, ee1, ee2, agg,
                                                  apply_bn, pg, pb);
        // agg[c] += bn_relu(h[r]) + ee(attr)  over real edges
        scatter_kernel<<<(Ee * 32) / 256, 256>>>(h, edge_index, edge_attr,
                                                 ee1, ee2, agg,
                                                 apply_bn, pg, pb);
        // hm1 = relu(agg @ W1[l] + b1[l])   [N,256]
        gemm_kernel<128, 128, 8, 8, 8, true>
            <<<dim3(2 * Dd / 128, Nn / 128), 256>>>(
                agg, W1 + (size_t)l * Dd * 2 * Dd, b1 + (size_t)l * 2 * Dd,
                hm1, Nn, 2 * Dd, Dd);
        // h(raw hm) = hm1 @ W2[l] + b2[l]   [N,128]
        gemm_kernel<128, 128, 8, 8, 8, false>
            <<<dim3(Dd / 128, Nn / 128), 256>>>(
                hm1, W2 + (size_t)l * 2 * Dd * Dd, b2 + (size_t)l * Dd,
                h, Nn, Dd, 2 * Dd);
        // column stats of raw hm (consumed by next layer's folded BN, or final norm)
        cudaMemsetAsync(stats, 0, 2 * Dd * sizeof(float), 0);
        bn_stats_kernel<<<Nn / BN_ROWS, Dd>>>(h);
        if (l == 4)
            bn_norm_kernel<<<(Nn * 32) / 256, 256>>>(h, out,
                                                     gamma + (size_t)4 * Dd,
                                                     beta + (size_t)4 * Dd);
    }
}

// round 6
// speedup vs baseline: 1.7120x; 1.7120x over previous
#include <cuda_runtime.h>
#include <cuda_fp16.h>
#include <cstdint>

#define Nn 131072
#define Ee 262144
#define Dd 128
#define EPS 1e-5f

// ---------------- scratch (no allocation allowed) ----------------
static __device__ float g_h  [(size_t)Nn * Dd];        // raw hm (gemm2 out) / h0
static __device__ float g_agg[(size_t)Nn * Dd];        // aggregation buffer
static __device__ float g_hm1[(size_t)Nn * 2 * Dd];    // gemm1 out
static __device__ float g_stats[2 * Dd];               // col sums / sumsq

// ---------------- h0 = x_emb1[x[:,0]] + x_emb2[x[:,1]] ----------------
__global__ void init_h_kernel(const int* __restrict__ x,
                              const float* __restrict__ emb1,
                              const float* __restrict__ emb2,
                              float* __restrict__ h)
{
    int idx = blockIdx.x * blockDim.x + threadIdx.x;   // Nn * 32 threads
    int n = idx >> 5;
    int j = (idx & 31) * 4;
    int i0 = x[2 * n];
    int i1 = x[2 * n + 1];
    float4 a = *(const float4*)&emb1[(size_t)i0 * Dd + j];
    float4 b = *(const float4*)&emb2[(size_t)i1 * Dd + j];
    float4 o = {a.x + b.x, a.y + b.y, a.z + b.z, a.w + b.w};
    *(float4*)&h[(size_t)n * Dd + j] = o;
}

// Apply previous layer's BatchNorm (+relu) on the fly when reading raw hm.
__device__ __forceinline__ float4 load_h_bn(const float* __restrict__ h,
                                            int node, int j, int apply_bn,
                                            const float* __restrict__ gamma,
                                            const float* __restrict__ beta)
{
    float4 v = *(const float4*)&h[(size_t)node * Dd + j];
    if (apply_bn) {
        const float inv_n = 1.0f / (float)Nn;
#pragma unroll
        for (int t = 0; t < 4; t++) {
            int cc = j + t;
            float mu  = g_stats[cc] * inv_n;
            float var = g_stats[Dd + cc] * inv_n - mu * mu;
            float sc  = rsqrtf(var + EPS) * gamma[cc];
            float sh  = beta[cc] - mu * sc;
            float val = ((const float*)&v)[t] * sc + sh;
            ((float*)&v)[t] = fmaxf(val, 0.f);   // layers 0..3 always relu
        }
    }
    return v;
}

// ---------------- agg init: self-loop message, plain store ----------------
__global__ void agg_init_kernel(const float* __restrict__ h,
                                const float* __restrict__ ee1,
                                const float* __restrict__ ee2,
                                float* __restrict__ agg, int apply_bn,
                                const float* __restrict__ gamma,
                                const float* __restrict__ beta)
{
    int idx = blockIdx.x * blockDim.x + threadIdx.x;
    int n = idx >> 5;
    int j = (idx & 31) * 4;
    float4 hv = load_h_bn(h, n, j, apply_bn, gamma, beta);
    float4 e1 = *(const float4*)&ee1[(size_t)4 * Dd + j];  // self-loop attr0 = 4
    float4 e2 = *(const float4*)&ee2[j];                   // self-loop attr1 = 0
    float4 o = {hv.x + e1.x + e2.x, hv.y + e1.y + e2.y,
                hv.z + e1.z + e2.z, hv.w + e1.w + e2.w};
    *(float4*)&agg[(size_t)n * Dd + j] = o;
}

// ---------------- edge message + scatter-add (one warp per edge) ----------------
__global__ void scatter_kernel(const float* __restrict__ h,
                               const int* __restrict__ edge_index,
                               const int* __restrict__ edge_attr,
                               const float* __restrict__ ee1,
                               const float* __restrict__ ee2,
                               float* __restrict__ agg, int apply_bn,
                               const float* __restrict__ gamma,
                               const float* __restrict__ beta)
{
    int warp = (blockIdx.x * blockDim.x + threadIdx.x) >> 5;
    int lane = threadIdx.x & 31;
    if (warp >= Ee) return;

    int r  = edge_index[warp];
    int c  = edge_index[Ee + warp];
    int a0 = edge_attr[2 * warp];
    int a1 = edge_attr[2 * warp + 1];

    int j = lane * 4;
    float4 hv = load_h_bn(h, r, j, apply_bn, gamma, beta);
    float4 e1 = *(const float4*)&ee1[(size_t)a0 * Dd + j];
    float4 e2 = *(const float4*)&ee2[(size_t)a1 * Dd + j];
    float4 v = {hv.x + e1.x + e2.x, hv.y + e1.y + e2.y,
                hv.z + e1.z + e2.z, hv.w + e1.w + e2.w};
    float* dst = &agg[(size_t)c * Dd + j];
    asm volatile("red.global.add.v4.f32 [%0], {%1, %2, %3, %4};"
                 :: "l"(dst), "f"(v.x), "f"(v.y), "f"(v.z), "f"(v.w)
                 : "memory");
}

// ================= fp16-split tensor-core GEMM ==========================
// C[M,Nc] = A[M,K] @ B[K,Nc] + bias (+relu), fp32 in/out.
// Each fp32 operand split into fp16 hi+lo; acc = hi*hi + hi*lo + lo*hi (fp32 accum).
// Per-element error ~2^-22 — far below the 1e-3 budget.

__device__ __forceinline__ void ldmA(uint32_t* r, const __half* p) {
    uint32_t a = (uint32_t)__cvta_generic_to_shared(p);
    asm volatile("ldmatrix.sync.aligned.m8n8.x4.shared.b16 {%0,%1,%2,%3}, [%4];"
                 : "=r"(r[0]), "=r"(r[1]), "=r"(r[2]), "=r"(r[3]) : "r"(a));
}
__device__ __forceinline__ void ldmBT(uint32_t* r, const __half* p) {
    uint32_t a = (uint32_t)__cvta_generic_to_shared(p);
    asm volatile("ldmatrix.sync.aligned.m8n8.x4.trans.shared.b16 {%0,%1,%2,%3}, [%4];"
                 : "=r"(r[0]), "=r"(r[1]), "=r"(r[2]), "=r"(r[3]) : "r"(a));
}
__device__ __forceinline__ void mma16816(float* c, const uint32_t* a, const uint32_t* b) {
    asm volatile(
        "mma.sync.aligned.m16n8k16.row.col.f32.f16.f16.f32 "
        "{%0,%1,%2,%3}, {%4,%5,%6,%7}, {%8,%9}, {%0,%1,%2,%3};\n"
        : "+f"(c[0]), "+f"(c[1]), "+f"(c[2]), "+f"(c[3])
        : "r"(a[0]), "r"(a[1]), "r"(a[2]), "r"(a[3]), "r"(b[0]), "r"(b[1]));
}

#define BM 128
#define BN 128
#define BK 32
#define A_LD 40    // (BK + 8) halfs; 80B rows: 16B-aligned, bank-staggered
#define B_LD 136   // (BN + 8) halfs; 272B rows: 16B-aligned

template<bool RELU>
__global__ __launch_bounds__(256, 2)
void gemm_mma_kernel(const float* __restrict__ A, const float* __restrict__ B,
                     const float* __restrict__ bias, float* __restrict__ C,
                     int M, int Nc, int K)
{
    __shared__ __half As_hi[BM * A_LD];
    __shared__ __half As_lo[BM * A_LD];
    __shared__ __half Bs_hi[BK * B_LD];
    __shared__ __half Bs_lo[BK * B_LD];

    const int tid  = threadIdx.x;
    const int lane = tid & 31;
    const int wid  = tid >> 5;             // 8 warps
    const int warp_m = (wid & 1) * 64;     // 2 warps in M
    const int warp_n = (wid >> 1) * 32;    // 4 warps in N
    const int rb = blockIdx.y * BM;
    const int cb = blockIdx.x * BN;

    float acc[4][4][4] = {};               // 4 m16-tiles x 4 n8-tiles

    for (int k0 = 0; k0 < K; k0 += BK) {
        // ---- load + split A tile (BM x BK) ----
#pragma unroll
        for (int it = 0; it < 4; it++) {
            int s = tid + it * 256;
            int row = s >> 3;
            int col = (s & 7) << 2;
            float4 v = *(const float4*)&A[(size_t)(rb + row) * K + k0 + col];
            const float* vp = (const float*)&v;
#pragma unroll
            for (int t = 0; t < 4; t++) {
                __half hh = __float2half_rn(vp[t]);
                __half ll = __float2half_rn(vp[t] - __half2float(hh));
                As_hi[row * A_LD + col + t] = hh;
                As_lo[row * A_LD + col + t] = ll;
            }
        }
        // ---- load + split B tile (BK x BN) ----
#pragma unroll
        for (int it = 0; it < 4; it++) {
            int s = tid + it * 256;
            int row = s >> 5;
            int col = (s & 31) << 2;
            float4 v = *(const float4*)&B[(size_t)(k0 + row) * Nc + cb + col];
            const float* vp = (const float*)&v;
#pragma unroll
            for (int t = 0; t < 4; t++) {
                __half hh = __float2half_rn(vp[t]);
                __half ll = __float2half_rn(vp[t] - __half2float(hh));
                Bs_hi[row * B_LD + col + t] = hh;
                Bs_lo[row * B_LD + col + t] = ll;
            }
        }
        __syncthreads();

#pragma unroll
        for (int kc = 0; kc < 2; kc++) {   // two k16 chunks per BK
            uint32_t af[4][4], bf[2][4];
            const int a_row = lane & 15;
            const int a_col = kc * 16 + (lane >> 4) * 8;
            const int bg    = lane >> 3;   // 0..3
            const int b_k   = kc * 16 + (bg & 1) * 8 + (lane & 7);
            // pass 1: hi * hi
#pragma unroll
            for (int i = 0; i < 4; i++)
                ldmA(af[i], &As_hi[(warp_m + i * 16 + a_row) * A_LD + a_col]);
#pragma unroll
            for (int j2 = 0; j2 < 2; j2++)
                ldmBT(bf[j2], &Bs_hi[b_k * B_LD + warp_n + j2 * 16 + (bg >> 1) * 8]);
#pragma unroll
            for (int i = 0; i < 4; i++)
#pragma unroll
                for (int j = 0; j < 4; j++)
                    mma16816(acc[i][j], af[i], &bf[j >> 1][(j & 1) * 2]);
            // pass 2: hi(A) * lo(B)  (af hi reused)
#pragma unroll
            for (int j2 = 0; j2 < 2; j2++)
                ldmBT(bf[j2], &Bs_lo[b_k * B_LD + warp_n + j2 * 16 + (bg >> 1) * 8]);
#pragma unroll
            for (int i = 0; i < 4; i++)
#pragma unroll
                for (int j = 0; j < 4; j++)
                    mma16816(acc[i][j], af[i], &bf[j >> 1][(j & 1) * 2]);
            // pass 3: lo(A) * hi(B)
#pragma unroll
            for (int i = 0; i < 4; i++)
                ldmA(af[i], &As_lo[(warp_m + i * 16 + a_row) * A_LD + a_col]);
#pragma unroll
            for (int j2 = 0; j2 < 2; j2++)
                ldmBT(bf[j2], &Bs_hi[b_k * B_LD + warp_n + j2 * 16 + (bg >> 1) * 8]);
#pragma unroll
            for (int i = 0; i < 4; i++)
#pragma unroll
                for (int j = 0; j < 4; j++)
                    mma16816(acc[i][j], af[i], &bf[j >> 1][(j & 1) * 2]);
        }
        __syncthreads();
    }

    // ---- epilogue: bias (+relu), direct fp32 stores ----
#pragma unroll
    for (int i = 0; i < 4; i++) {
        int r0 = rb + warp_m + i * 16 + (lane >> 2);
#pragma unroll
        for (int j = 0; j < 4; j++) {
            int c0 = cb + warp_n + j * 8 + (lane & 3) * 2;
            float bx = bias[c0], by = bias[c0 + 1];
#pragma unroll
            for (int half_ = 0; half_ < 2; half_++) {
                int r = r0 + half_ * 8;
                float vx = acc[i][j][half_ * 2 + 0] + bx;
                float vy = acc[i][j][half_ * 2 + 1] + by;
                if (RELU) { vx = fmaxf(vx, 0.f); vy = fmaxf(vy, 0.f); }
                float2 o = {vx, vy};
                *(float2*)&C[(size_t)r * Nc + c0] = o;
            }
        }
    }
}

// ---------------- BatchNorm column stats (sum, sumsq) ----------------
#define BN_ROWS 128
__global__ void bn_stats_kernel(const float* __restrict__ X)
{
    int c = threadIdx.x;                  // 0..127
    size_t r0 = (size_t)blockIdx.x * BN_ROWS;
    float s = 0.f, ss = 0.f;
#pragma unroll 8
    for (int r = 0; r < BN_ROWS; r++) {
        float v = X[(r0 + r) * Dd + c];
        s += v;
        ss += v * v;
    }
    atomicAdd(&g_stats[c], s);
    atomicAdd(&g_stats[Dd + c], ss);
}

// ---------------- final BatchNorm normalize (no relu), layer 4 only ----------------
__global__ void bn_norm_kernel(const float* __restrict__ X, float* __restrict__ Y,
                               const float* __restrict__ gamma,
                               const float* __restrict__ beta)
{
    int idx = blockIdx.x * blockDim.x + threadIdx.x;
    int n = idx >> 5;
    int c = (idx & 31) * 4;
    const float inv_n = 1.0f / (float)Nn;
    float4 v = *(const float4*)&X[(size_t)n * Dd + c];
    float4 o;
#pragma unroll
    for (int t = 0; t < 4; t++) {
        int cc = c + t;
        float mu  = g_stats[cc] * inv_n;
        float var = g_stats[Dd + cc] * inv_n - mu * mu;
        float sc = rsqrtf(var + EPS) * gamma[cc];
        float sh = beta[cc] - mu * sc;
        ((float*)&o)[t] = ((const float*)&v)[t] * sc + sh;
    }
    *(float4*)&Y[(size_t)n * Dd + c] = o;
}

// ---------------- driver ----------------
extern "C" void kernel_launch(void* const* d_in, const int* in_sizes, int n_in,
                              void* d_out, int out_size)
{
    const int*   x          = (const int*)  d_in[0];
    const int*   edge_index = (const int*)  d_in[1];
    const int*   edge_attr  = (const int*)  d_in[2];
    const float* x_emb1     = (const float*)d_in[3];
    const float* x_emb2     = (const float*)d_in[4];
    const float* e_emb1     = (const float*)d_in[5];   // [5,6,128]
    const float* e_emb2     = (const float*)d_in[6];   // [5,3,128]
    const float* W1         = (const float*)d_in[7];   // [5,128,256]
    const float* b1         = (const float*)d_in[8];   // [5,256]
    const float* W2         = (const float*)d_in[9];   // [5,256,128]
    const float* b2         = (const float*)d_in[10];  // [5,128]
    const float* gamma      = (const float*)d_in[11];  // [5,128]
    const float* beta       = (const float*)d_in[12];  // [5,128]
    float* out = (float*)d_out;

    float *h, *agg, *hm1, *stats;
    cudaGetSymbolAddress((void**)&h,     g_h);
    cudaGetSymbolAddress((void**)&agg,   g_agg);
    cudaGetSymbolAddress((void**)&hm1,   g_hm1);
    cudaGetSymbolAddress((void**)&stats, g_stats);

    init_h_kernel<<<(Nn * 32) / 256, 256>>>(x, x_emb1, x_emb2, h);

    for (int l = 0; l < 5; l++) {
        const float* ee1 = e_emb1 + (size_t)l * 6 * Dd;
        const float* ee2 = e_emb2 + (size_t)l * 3 * Dd;
        const float* pg = gamma + (size_t)(l > 0 ? l - 1 : 0) * Dd;
        const float* pb = beta  + (size_t)(l > 0 ? l - 1 : 0) * Dd;
        int apply_bn = (l > 0) ? 1 : 0;

        agg_init_kernel<<<(Nn * 32) / 256, 256>>>(h, ee1, ee2, agg,
                                                  apply_bn, pg, pb);
        scatter_kernel<<<(Ee * 32) / 256, 256>>>(h, edge_index, edge_attr,
                                                 ee1, ee2, agg,
                                                 apply_bn, pg, pb);
        // hm1 = relu(agg @ W1[l] + b1[l])   [N,256]
        gemm_mma_kernel<true><<<dim3(2 * Dd / BN, Nn / BM), 256>>>(
            agg, W1 + (size_t)l * Dd * 2 * Dd, b1 + (size_t)l * 2 * Dd,
            hm1, Nn, 2 * Dd, Dd);
        // h(raw hm) = hm1 @ W2[l] + b2[l]   [N,128]
        gemm_mma_kernel<false><<<dim3(Dd / BN, Nn / BM), 256>>>(
            hm1, W2 + (size_t)l * 2 * Dd * Dd, b2 + (size_t)l * Dd,
            h, Nn, Dd, 2 * Dd);
        cudaMemsetAsync(stats, 0, 2 * Dd * sizeof(float), 0);
        bn_stats_kernel<<<Nn / BN_ROWS, Dd>>>(h);
        if (l == 4)
            bn_norm_kernel<<<(Nn * 32) / 256, 256>>>(h, out,
                                                     gamma + (size_t)4 * Dd,
                                                     beta + (size_t)4 * Dd);
    }
}

// round 9
// speedup vs baseline: 1.7200x; 1.0047x over previous
#include <cuda_runtime.h>
#include <cuda_fp16.h>
#include <cstdint>

#define Nn 131072
#define Ee 262144
#define Dd 128
#define EPS 1e-5f

// ---------------- scratch (no allocation allowed) ----------------
static __device__ float  g_h  [(size_t)Nn * Dd];          // raw hm (gemm2 out) / h0
static __device__ float  g_agg[(size_t)Nn * Dd];          // aggregation buffer
static __device__ __half g_hm1_hi[(size_t)Nn * 2 * Dd];   // gemm1 out, hi halves
static __device__ __half g_hm1_lo[(size_t)Nn * 2 * Dd];   // gemm1 out, lo halves
static __device__ __half g_w1_hi[5 * Dd * 2 * Dd];
static __device__ __half g_w1_lo[5 * Dd * 2 * Dd];
static __device__ __half g_w2_hi[5 * 2 * Dd * Dd];
static __device__ __half g_w2_lo[5 * 2 * Dd * Dd];
static __device__ float  g_stats[2 * Dd];                 // col sums / sumsq

// ---------------- weight split prep (runs once per call, tiny) ----------------
__global__ void split_weights_kernel(const float* __restrict__ W1,
                                     const float* __restrict__ W2)
{
    int i = blockIdx.x * blockDim.x + threadIdx.x;   // 5*128*256 = 163840 each
    float a = W1[i];
    __half ah = __float2half_rn(a);
    g_w1_hi[i] = ah;
    g_w1_lo[i] = __float2half_rn(a - __half2float(ah));
    float b = W2[i];
    __half bh = __float2half_rn(b);
    g_w2_hi[i] = bh;
    g_w2_lo[i] = __float2half_rn(b - __half2float(bh));
}

// ---------------- h0 = x_emb1[x[:,0]] + x_emb2[x[:,1]] ----------------
__global__ void init_h_kernel(const int* __restrict__ x,
                              const float* __restrict__ emb1,
                              const float* __restrict__ emb2,
                              float* __restrict__ h)
{
    int idx = blockIdx.x * blockDim.x + threadIdx.x;   // Nn * 32 threads
    int n = idx >> 5;
    int j = (idx & 31) * 4;
    int i0 = x[2 * n];
    int i1 = x[2 * n + 1];
    float4 a = *(const float4*)&emb1[(size_t)i0 * Dd + j];
    float4 b = *(const float4*)&emb2[(size_t)i1 * Dd + j];
    float4 o = {a.x + b.x, a.y + b.y, a.z + b.z, a.w + b.w};
    *(float4*)&h[(size_t)n * Dd + j] = o;
}

// Apply previous layer's BatchNorm (+relu) on the fly when reading raw hm.
__device__ __forceinline__ float4 load_h_bn(const float* __restrict__ h,
                                            int node, int j, int apply_bn,
                                            const float* __restrict__ gamma,
                                            const float* __restrict__ beta)
{
    float4 v = *(const float4*)&h[(size_t)node * Dd + j];
    if (apply_bn) {
        const float inv_n = 1.0f / (float)Nn;
#pragma unroll
        for (int t = 0; t < 4; t++) {
            int cc = j + t;
            float mu  = g_stats[cc] * inv_n;
            float var = g_stats[Dd + cc] * inv_n - mu * mu;
            float sc  = rsqrtf(var + EPS) * gamma[cc];
            float sh  = beta[cc] - mu * sc;
            float val = ((const float*)&v)[t] * sc + sh;
            ((float*)&v)[t] = fmaxf(val, 0.f);   // layers 0..3 always relu
        }
    }
    return v;
}

// ---------------- agg init: self-loop message, plain store ----------------
__global__ void agg_init_kernel(const float* __restrict__ h,
                                const float* __restrict__ ee1,
                                const float* __restrict__ ee2,
                                float* __restrict__ agg, int apply_bn,
                                const float* __restrict__ gamma,
                                const float* __restrict__ beta)
{
    int idx = blockIdx.x * blockDim.x + threadIdx.x;
    int n = idx >> 5;
    int j = (idx & 31) * 4;
    float4 hv = load_h_bn(h, n, j, apply_bn, gamma, beta);
    float4 e1 = *(const float4*)&ee1[(size_t)4 * Dd + j];  // self-loop attr0 = 4
    float4 e2 = *(const float4*)&ee2[j];                   // self-loop attr1 = 0
    float4 o = {hv.x + e1.x + e2.x, hv.y + e1.y + e2.y,
                hv.z + e1.z + e2.z, hv.w + e1.w + e2.w};
    *(float4*)&agg[(size_t)n * Dd + j] = o;
}

// ---------------- edge message + scatter-add (one warp per edge) ----------------
__global__ void scatter_kernel(const float* __restrict__ h,
                               const int* __restrict__ edge_index,
                               const int* __restrict__ edge_attr,
                               const float* __restrict__ ee1,
                               const float* __restrict__ ee2,
                               float* __restrict__ agg, int apply_bn,
                               const float* __restrict__ gamma,
                               const float* __restrict__ beta)
{
    int warp = (blockIdx.x * blockDim.x + threadIdx.x) >> 5;
    int lane = threadIdx.x & 31;
    if (warp >= Ee) return;

    int r  = edge_index[warp];
    int c  = edge_index[Ee + warp];
    int a0 = edge_attr[2 * warp];
    int a1 = edge_attr[2 * warp + 1];

    int j = lane * 4;
    float4 hv = load_h_bn(h, r, j, apply_bn, gamma, beta);
    float4 e1 = *(const float4*)&ee1[(size_t)a0 * Dd + j];
    float4 e2 = *(const float4*)&ee2[(size_t)a1 * Dd + j];
    float4 v = {hv.x + e1.x + e2.x, hv.y + e1.y + e2.y,
                hv.z + e1.z + e2.z, hv.w + e1.w + e2.w};
    float* dst = &agg[(size_t)c * Dd + j];
    asm volatile("red.global.add.v4.f32 [%0], {%1, %2, %3, %4};"
                 :: "l"(dst), "f"(v.x), "f"(v.y), "f"(v.z), "f"(v.w)
                 : "memory");
}

// ================= fp16-split tensor-core GEMM ==========================
// C = A @ B + bias (+relu); acc = Ahi*Bhi + Ahi*Blo + Alo*Bhi (fp32 accum).
// AHALF: A pre-split half arrays (pure copy path). Else fp32 A split in-kernel.
// SPLITOUT: epilogue writes hi/lo half arrays (consumed by next AHALF GEMM).

__device__ __forceinline__ void ldmA(uint32_t* r, const __half* p) {
    uint32_t a = (uint32_t)__cvta_generic_to_shared(p);
    asm volatile("ldmatrix.sync.aligned.m8n8.x4.shared.b16 {%0,%1,%2,%3}, [%4];"
                 : "=r"(r[0]), "=r"(r[1]), "=r"(r[2]), "=r"(r[3]) : "r"(a));
}
__device__ __forceinline__ void ldmBT(uint32_t* r, const __half* p) {
    uint32_t a = (uint32_t)__cvta_generic_to_shared(p);
    asm volatile("ldmatrix.sync.aligned.m8n8.x4.trans.shared.b16 {%0,%1,%2,%3}, [%4];"
                 : "=r"(r[0]), "=r"(r[1]), "=r"(r[2]), "=r"(r[3]) : "r"(a));
}
__device__ __forceinline__ void mma16816(float* c, const uint32_t* a, const uint32_t* b) {
    asm volatile(
        "mma.sync.aligned.m16n8k16.row.col.f32.f16.f16.f32 "
        "{%0,%1,%2,%3}, {%4,%5,%6,%7}, {%8,%9}, {%0,%1,%2,%3};\n"
        : "+f"(c[0]), "+f"(c[1]), "+f"(c[2]), "+f"(c[3])
        : "r"(a[0]), "r"(a[1]), "r"(a[2]), "r"(a[3]), "r"(b[0]), "r"(b[1]));
}

#define BM 128
#define BN 128
#define BK 32
#define A_LD 40    // (BK + 8) halfs; 80B rows
#define B_LD 136   // (BN + 8) halfs; 272B rows

template<bool AHALF, bool RELU, bool SPLITOUT>
__global__ __launch_bounds__(256, 2)
void gemm_mma_kernel(const float* __restrict__ Af,
                     const __half* __restrict__ Ah, const __half* __restrict__ Al,
                     const __half* __restrict__ Bh, const __half* __restrict__ Bl,
                     const float* __restrict__ bias,
                     float* __restrict__ Cf,
                     __half* __restrict__ Ch, __half* __restrict__ Cl,
                     int M, int Nc, int K)
{
    __shared__ __half As_hi[BM * A_LD];
    __shared__ __half As_lo[BM * A_LD];
    __shared__ __half Bs_hi[BK * B_LD];
    __shared__ __half Bs_lo[BK * B_LD];

    const int tid  = threadIdx.x;
    const int lane = tid & 31;
    const int wid  = tid >> 5;             // 8 warps
    const int warp_m = (wid & 1) * 64;     // 2 warps in M
    const int warp_n = (wid >> 1) * 32;    // 4 warps in N
    const int rb = blockIdx.y * BM;
    const int cb = blockIdx.x * BN;

    float acc[4][4][4] = {};               // 4 m16-tiles x 4 n8-tiles

    for (int k0 = 0; k0 < K; k0 += BK) {
        // ---- A tile (BM x BK halfs, hi+lo) ----
        if (AHALF) {
#pragma unroll
            for (int it = 0; it < 2; it++) {
                int c = tid + it * 256;            // 512 chunks of 8 halfs
                int row = c >> 2;
                int col = (c & 3) * 8;
                *(uint4*)&As_hi[row * A_LD + col] =
                    *(const uint4*)&Ah[(size_t)(rb + row) * K + k0 + col];
                *(uint4*)&As_lo[row * A_LD + col] =
                    *(const uint4*)&Al[(size_t)(rb + row) * K + k0 + col];
            }
        } else {
#pragma unroll
            for (int it = 0; it < 4; it++) {
                int s = tid + it * 256;            // 1024 chunks of 4 floats
                int row = s >> 3;
                int col = (s & 7) * 4;
                float4 v = *(const float4*)&Af[(size_t)(rb + row) * K + k0 + col];
                __half2 h01 = __floats2half2_rn(v.x, v.y);
                __half2 h23 = __floats2half2_rn(v.z, v.w);
                float2 f01 = __half22float2(h01);
                float2 f23 = __half22float2(h23);
                __half2 l01 = __floats2half2_rn(v.x - f01.x, v.y - f01.y);
                __half2 l23 = __floats2half2_rn(v.z - f23.x, v.w - f23.y);
                uint2 uh, ul;
                uh.x = *(const uint32_t*)&h01; uh.y = *(const uint32_t*)&h23;
                ul.x = *(const uint32_t*)&l01; ul.y = *(const uint32_t*)&l23;
                *(uint2*)&As_hi[row * A_LD + col] = uh;
                *(uint2*)&As_lo[row * A_LD + col] = ul;
            }
        }
        // ---- B tile (BK x BN halfs, hi+lo), pure copy ----
#pragma unroll
        for (int it = 0; it < 2; it++) {
            int c = tid + it * 256;                // 512 chunks of 8 halfs
            int row = c >> 4;
            int col = (c & 15) * 8;
            *(uint4*)&Bs_hi[row * B_LD + col] =
                *(const uint4*)&Bh[(size_t)(k0 + row) * Nc + cb + col];
            *(uint4*)&Bs_lo[row * B_LD + col] =
                *(const uint4*)&Bl[(size_t)(k0 + row) * Nc + cb + col];
        }
        __syncthreads();

#pragma unroll
        for (int kc = 0; kc < 2; kc++) {   // two k16 chunks per BK
            uint32_t af[4][4], bfh[2][4], bfl[2][4];
            const int a_row = lane & 15;
            const int a_col = kc * 16 + (lane >> 4) * 8;
            const int bg    = lane >> 3;   // 0..3
            const int b_k   = kc * 16 + (bg & 1) * 8 + (lane & 7);
            // load B hi + lo fragments (kept in regs across passes)
#pragma unroll
            for (int j2 = 0; j2 < 2; j2++) {
                ldmBT(bfh[j2], &Bs_hi[b_k * B_LD + warp_n + j2 * 16 + (bg >> 1) * 8]);
                ldmBT(bfl[j2], &Bs_lo[b_k * B_LD + warp_n + j2 * 16 + (bg >> 1) * 8]);
            }
            // pass 1: hi(A) * hi(B)
#pragma unroll
            for (int i = 0; i < 4; i++)
                ldmA(af[i], &As_hi[(warp_m + i * 16 + a_row) * A_LD + a_col]);
#pragma unroll
            for (int i = 0; i < 4; i++)
#pragma unroll
                for (int j = 0; j < 4; j++)
                    mma16816(acc[i][j], af[i], &bfh[j >> 1][(j & 1) * 2]);
            // pass 2: hi(A) * lo(B)  (af reused)
#pragma unroll
            for (int i = 0; i < 4; i++)
#pragma unroll
                for (int j = 0; j < 4; j++)
                    mma16816(acc[i][j], af[i], &bfl[j >> 1][(j & 1) * 2]);
            // pass 3: lo(A) * hi(B)
#pragma unroll
            for (int i = 0; i < 4; i++)
                ldmA(af[i], &As_lo[(warp_m + i * 16 + a_row) * A_LD + a_col]);
#pragma unroll
            for (int i = 0; i < 4; i++)
#pragma unroll
                for (int j = 0; j < 4; j++)
                    mma16816(acc[i][j], af[i], &bfh[j >> 1][(j & 1) * 2]);
        }
        __syncthreads();
    }

    // ---- epilogue: bias (+relu), fp32 or split-half stores ----
#pragma unroll
    for (int i = 0; i < 4; i++) {
        int r0 = rb + warp_m + i * 16 + (lane >> 2);
#pragma unroll
        for (int j = 0; j < 4; j++) {
            int c0 = cb + warp_n + j * 8 + (lane & 3) * 2;
            float bx = bias[c0], by = bias[c0 + 1];
#pragma unroll
            for (int half_ = 0; half_ < 2; half_++) {
                int r = r0 + half_ * 8;
                float vx = acc[i][j][half_ * 2 + 0] + bx;
                float vy = acc[i][j][half_ * 2 + 1] + by;
                if (RELU) { vx = fmaxf(vx, 0.f); vy = fmaxf(vy, 0.f); }
                if (SPLITOUT) {
                    __half2 hp = __floats2half2_rn(vx, vy);
                    float2 fp = __half22float2(hp);
                    __half2 lp = __floats2half2_rn(vx - fp.x, vy - fp.y);
                    *(__half2*)&Ch[(size_t)r * Nc + c0] = hp;
                    *(__half2*)&Cl[(size_t)r * Nc + c0] = lp;
                } else {
                    float2 o = {vx, vy};
                    *(float2*)&Cf[(size_t)r * Nc + c0] = o;
                }
            }
        }
    }
}

// ---------------- BatchNorm column stats (sum, sumsq) ----------------
#define BN_ROWS 128
__global__ void bn_stats_kernel(const float* __restrict__ X)
{
    int c = threadIdx.x;                  // 0..127
    size_t r0 = (size_t)blockIdx.x * BN_ROWS;
    float s = 0.f, ss = 0.f;
#pragma unroll 8
    for (int r = 0; r < BN_ROWS; r++) {
        float v = X[(r0 + r) * Dd + c];
        s += v;
        ss += v * v;
    }
    atomicAdd(&g_stats[c], s);
    atomicAdd(&g_stats[Dd + c], ss);
}

// ---------------- final BatchNorm normalize (no relu), layer 4 only ----------------
__global__ void bn_norm_kernel(const float* __restrict__ X, float* __restrict__ Y,
                               const float* __restrict__ gamma,
                               const float* __restrict__ beta)
{
    int idx = blockIdx.x * blockDim.x + threadIdx.x;
    int n = idx >> 5;
    int c = (idx & 31) * 4;
    const float inv_n = 1.0f / (float)Nn;
    float4 v = *(const float4*)&X[(size_t)n * Dd + c];
    float4 o;
#pragma unroll
    for (int t = 0; t < 4; t++) {
        int cc = c + t;
        float mu  = g_stats[cc] * inv_n;
        float var = g_stats[Dd + cc] * inv_n - mu * mu;
        float sc = rsqrtf(var + EPS) * gamma[cc];
        float sh = beta[cc] - mu * sc;
        ((float*)&o)[t] = ((const float*)&v)[t] * sc + sh;
    }
    *(float4*)&Y[(size_t)n * Dd + c] = o;
}

// ---------------- driver ----------------
extern "C" void kernel_launch(void* const* d_in, const int* in_sizes, int n_in,
                              void* d_out, int out_size)
{
    const int*   x          = (const int*)  d_in[0];
    const int*   edge_index = (const int*)  d_in[1];
    const int*   edge_attr  = (const int*)  d_in[2];
    const float* x_emb1     = (const float*)d_in[3];
    const float* x_emb2     = (const float*)d_in[4];
    const float* e_emb1     = (const float*)d_in[5];   // [5,6,128]
    const float* e_emb2     = (const float*)d_in[6];   // [5,3,128]
    const float* W1         = (const float*)d_in[7];   // [5,128,256]
    const float* b1         = (const float*)d_in[8];   // [5,256]
    const float* W2         = (const float*)d_in[9];   // [5,256,128]
    const float* b2         = (const float*)d_in[10];  // [5,128]
    const float* gamma      = (const float*)d_in[11];  // [5,128]
    const float* beta       = (const float*)d_in[12];  // [5,128]
    float* out = (float*)d_out;

    float *h, *agg, *stats;
    __half *hm1h, *hm1l, *w1h, *w1l, *w2h, *w2l;
    cudaGetSymbolAddress((void**)&h,     g_h);
    cudaGetSymbolAddress((void**)&agg,   g_agg);
    cudaGetSymbolAddress((void**)&hm1h,  g_hm1_hi);
    cudaGetSymbolAddress((void**)&hm1l,  g_hm1_lo);
    cudaGetSymbolAddress((void**)&w1h,   g_w1_hi);
    cudaGetSymbolAddress((void**)&w1l,   g_w1_lo);
    cudaGetSymbolAddress((void**)&w2h,   g_w2_hi);
    cudaGetSymbolAddress((void**)&w2l,   g_w2_lo);
    cudaGetSymbolAddress((void**)&stats, g_stats);

    split_weights_kernel<<<(5 * Dd * 2 * Dd) / 256, 256>>>(W1, W2);
    init_h_kernel<<<(Nn * 32) / 256, 256>>>(x, x_emb1, x_emb2, h);

    for (int l = 0; l < 5; l++) {
        const float* ee1 = e_emb1 + (size_t)l * 6 * Dd;
        const float* ee2 = e_emb2 + (size_t)l * 3 * Dd;
        const float* pg = gamma + (size_t)(l > 0 ? l - 1 : 0) * Dd;
        const float* pb = beta  + (size_t)(l > 0 ? l - 1 : 0) * Dd;
        int apply_bn = (l > 0) ? 1 : 0;

        agg_init_kernel<<<(Nn * 32) / 256, 256>>>(h, ee1, ee2, agg,
                                                  apply_bn, pg, pb);
        scatter_kernel<<<(Ee * 32) / 256, 256>>>(h, edge_index, edge_attr,
                                                 ee1, ee2, agg,
                                                 apply_bn, pg, pb);
        // hm1(hi,lo) = relu(agg @ W1[l] + b1[l])   [N,256]
        gemm_mma_kernel<false, true, true>
            <<<dim3(2 * Dd / BN, Nn / BM), 256>>>(
                agg, nullptr, nullptr,
                w1h + (size_t)l * Dd * 2 * Dd, w1l + (size_t)l * Dd * 2 * Dd,
                b1 + (size_t)l * 2 * Dd,
                nullptr, hm1h, hm1l, Nn, 2 * Dd, Dd);
        // h(raw hm) = hm1 @ W2[l] + b2[l]   [N,128]
        gemm_mma_kernel<true, false, false>
            <<<dim3(Dd / BN, Nn / BM), 256>>>(
                nullptr, hm1h, hm1l,
                w2h + (size_t)l * 2 * Dd * Dd, w2l + (size_t)l * 2 * Dd * Dd,
                b2 + (size_t)l * Dd,
                h, nullptr, nullptr, Nn, Dd, 2 * Dd);
        cudaMemsetAsync(stats, 0, 2 * Dd * sizeof(float), 0);
        bn_stats_kernel<<<Nn / BN_ROWS, Dd>>>(h);
        if (l == 4)
            bn_norm_kernel<<<(Nn * 32) / 256, 256>>>(h, out,
                                                     gamma + (size_t)4 * Dd,
                                                     beta + (size_t)4 * Dd);
    }
}

// round 11
// speedup vs baseline: 1.7314x; 1.0066x over previous
#include <cuda_runtime.h>
#include <cuda_fp16.h>
#include <cstdint>

#define Nn 131072
#define Ee 262144
#define Dd 128
#define EPS 1e-5f

// ---------------- scratch (no allocation allowed) ----------------
static __device__ float  g_h  [(size_t)Nn * Dd];          // raw hm (gemm2 out) / h0
static __device__ float  g_agg[(size_t)Nn * Dd];          // aggregation buffer (fp32, atomics)
static __device__ __half g_agg_hi[(size_t)Nn * Dd];       // agg split hi
static __device__ __half g_agg_lo[(size_t)Nn * Dd];       // agg split lo
static __device__ __half g_hm1_hi[(size_t)Nn * 2 * Dd];   // gemm1 out, hi halves
static __device__ __half g_hm1_lo[(size_t)Nn * 2 * Dd];   // gemm1 out, lo halves
static __device__ __half g_w1_hi[5 * Dd * 2 * Dd];
static __device__ __half g_w1_lo[5 * Dd * 2 * Dd];
static __device__ __half g_w2_hi[5 * 2 * Dd * Dd];
static __device__ __half g_w2_lo[5 * 2 * Dd * Dd];
static __device__ float  g_stats[2 * Dd];                 // col sums / sumsq

// ---------------- weight split prep (runs once per call, tiny) ----------------
__global__ void split_weights_kernel(const float* __restrict__ W1,
                                     const float* __restrict__ W2)
{
    int i = blockIdx.x * blockDim.x + threadIdx.x;   // 5*128*256 = 163840 each
    float a = W1[i];
    __half ah = __float2half_rn(a);
    g_w1_hi[i] = ah;
    g_w1_lo[i] = __float2half_rn(a - __half2float(ah));
    float b = W2[i];
    __half bh = __float2half_rn(b);
    g_w2_hi[i] = bh;
    g_w2_lo[i] = __float2half_rn(b - __half2float(bh));
}

// ---------------- split agg fp32 -> hi/lo halves ----------------
__global__ void split_agg_kernel(const float* __restrict__ agg,
                                 __half* __restrict__ ah, __half* __restrict__ al)
{
    int idx = blockIdx.x * blockDim.x + threadIdx.x;    // Nn*Dd/4 threads
    size_t i4 = (size_t)idx * 4;
    float4 v = *(const float4*)&agg[i4];
    __half2 h01 = __floats2half2_rn(v.x, v.y);
    __half2 h23 = __floats2half2_rn(v.z, v.w);
    float2 f01 = __half22float2(h01);
    float2 f23 = __half22float2(h23);
    __half2 l01 = __floats2half2_rn(v.x - f01.x, v.y - f01.y);
    __half2 l23 = __floats2half2_rn(v.z - f23.x, v.w - f23.y);
    uint2 uh, ul;
    uh.x = *(const uint32_t*)&h01; uh.y = *(const uint32_t*)&h23;
    ul.x = *(const uint32_t*)&l01; ul.y = *(const uint32_t*)&l23;
    *(uint2*)&ah[i4] = uh;
    *(uint2*)&al[i4] = ul;
}

// ---------------- h0 = x_emb1[x[:,0]] + x_emb2[x[:,1]] ----------------
__global__ void init_h_kernel(const int* __restrict__ x,
                              const float* __restrict__ emb1,
                              const float* __restrict__ emb2,
                              float* __restrict__ h)
{
    int idx = blockIdx.x * blockDim.x + threadIdx.x;   // Nn * 32 threads
    int n = idx >> 5;
    int j = (idx & 31) * 4;
    int i0 = x[2 * n];
    int i1 = x[2 * n + 1];
    float4 a = *(const float4*)&emb1[(size_t)i0 * Dd + j];
    float4 b = *(const float4*)&emb2[(size_t)i1 * Dd + j];
    float4 o = {a.x + b.x, a.y + b.y, a.z + b.z, a.w + b.w};
    *(float4*)&h[(size_t)n * Dd + j] = o;
}

// Apply previous layer's BatchNorm (+relu) on the fly when reading raw hm.
__device__ __forceinline__ float4 load_h_bn(const float* __restrict__ h,
                                            int node, int j, int apply_bn,
                                            const float* __restrict__ gamma,
                                            const float* __restrict__ beta)
{
    float4 v = *(const float4*)&h[(size_t)node * Dd + j];
    if (apply_bn) {
        const float inv_n = 1.0f / (float)Nn;
#pragma unroll
        for (int t = 0; t < 4; t++) {
            int cc = j + t;
            float mu  = g_stats[cc] * inv_n;
            float var = g_stats[Dd + cc] * inv_n - mu * mu;
            float sc  = rsqrtf(var + EPS) * gamma[cc];
            float sh  = beta[cc] - mu * sc;
            float val = ((const float*)&v)[t] * sc + sh;
            ((float*)&v)[t] = fmaxf(val, 0.f);   // layers 0..3 always relu
        }
    }
    return v;
}

// ---------------- agg init: self-loop message, plain store ----------------
__global__ void agg_init_kernel(const float* __restrict__ h,
                                const float* __restrict__ ee1,
                                const float* __restrict__ ee2,
                                float* __restrict__ agg, int apply_bn,
                                const float* __restrict__ gamma,
                                const float* __restrict__ beta)
{
    int idx = blockIdx.x * blockDim.x + threadIdx.x;
    int n = idx >> 5;
    int j = (idx & 31) * 4;
    float4 hv = load_h_bn(h, n, j, apply_bn, gamma, beta);
    float4 e1 = *(const float4*)&ee1[(size_t)4 * Dd + j];  // self-loop attr0 = 4
    float4 e2 = *(const float4*)&ee2[j];                   // self-loop attr1 = 0
    float4 o = {hv.x + e1.x + e2.x, hv.y + e1.y + e2.y,
                hv.z + e1.z + e2.z, hv.w + e1.w + e2.w};
    *(float4*)&agg[(size_t)n * Dd + j] = o;
}

// ---------------- edge message + scatter-add (one warp per edge) ----------------
__global__ void scatter_kernel(const float* __restrict__ h,
                               const int* __restrict__ edge_index,
                               const int* __restrict__ edge_attr,
                               const float* __restrict__ ee1,
                               const float* __restrict__ ee2,
                               float* __restrict__ agg, int apply_bn,
                               const float* __restrict__ gamma,
                               const float* __restrict__ beta)
{
    int warp = (blockIdx.x * blockDim.x + threadIdx.x) >> 5;
    int lane = threadIdx.x & 31;
    if (warp >= Ee) return;

    int r  = edge_index[warp];
    int c  = edge_index[Ee + warp];
    int a0 = edge_attr[2 * warp];
    int a1 = edge_attr[2 * warp + 1];

    int j = lane * 4;
    float4 hv = load_h_bn(h, r, j, apply_bn, gamma, beta);
    float4 e1 = *(const float4*)&ee1[(size_t)a0 * Dd + j];
    float4 e2 = *(const float4*)&ee2[(size_t)a1 * Dd + j];
    float4 v = {hv.x + e1.x + e2.x, hv.y + e1.y + e2.y,
                hv.z + e1.z + e2.z, hv.w + e1.w + e2.w};
    float* dst = &agg[(size_t)c * Dd + j];
    asm volatile("red.global.add.v4.f32 [%0], {%1, %2, %3, %4};"
                 :: "l"(dst), "f"(v.x), "f"(v.y), "f"(v.z), "f"(v.w)
                 : "memory");
}

// ================= fp16-split tensor-core GEMM (cp.async 2-stage) ========
// C = A @ B + bias (+relu); acc = Ahi*Bhi + Ahi*Blo + Alo*Bhi (fp32 accum).
// All operands pre-split halves; tile loads are pure 16B cp.async copies,
// double-buffered so stage k+1 global loads overlap stage k compute.

__device__ __forceinline__ void ldmA(uint32_t* r, const __half* p) {
    uint32_t a = (uint32_t)__cvta_generic_to_shared(p);
    asm volatile("ldmatrix.sync.aligned.m8n8.x4.shared.b16 {%0,%1,%2,%3}, [%4];"
                 : "=r"(r[0]), "=r"(r[1]), "=r"(r[2]), "=r"(r[3]) : "r"(a));
}
__device__ __forceinline__ void ldmBT(uint32_t* r, const __half* p) {
    uint32_t a = (uint32_t)__cvta_generic_to_shared(p);
    asm volatile("ldmatrix.sync.aligned.m8n8.x4.trans.shared.b16 {%0,%1,%2,%3}, [%4];"
                 : "=r"(r[0]), "=r"(r[1]), "=r"(r[2]), "=r"(r[3]) : "r"(a));
}
__device__ __forceinline__ void mma16816(float* c, const uint32_t* a, const uint32_t* b) {
    asm volatile(
        "mma.sync.aligned.m16n8k16.row.col.f32.f16.f16.f32 "
        "{%0,%1,%2,%3}, {%4,%5,%6,%7}, {%8,%9}, {%0,%1,%2,%3};\n"
        : "+f"(c[0]), "+f"(c[1]), "+f"(c[2]), "+f"(c[3])
        : "r"(a[0]), "r"(a[1]), "r"(a[2]), "r"(a[3]), "r"(b[0]), "r"(b[1]));
}
__device__ __forceinline__ void cpa16(__half* dst, const __half* src) {
    uint32_t d = (uint32_t)__cvta_generic_to_shared(dst);
    asm volatile("cp.async.cg.shared.global [%0], [%1], 16;" :: "r"(d), "l"(src));
}

#define BM 128
#define BN 128
#define BK 32
#define A_LD 40    // (BK + 8) halfs; 80B rows
#define B_LD 136   // (BN + 8) halfs; 272B rows
#define A_SZ (BM * A_LD)
#define B_SZ (BK * B_LD)

template<bool RELU, bool SPLITOUT>
__global__ __launch_bounds__(256, 2)
void gemm_mma_kernel(const __half* __restrict__ Ah, const __half* __restrict__ Al,
                     const __half* __restrict__ Bh, const __half* __restrict__ Bl,
                     const float* __restrict__ bias,
                     float* __restrict__ Cf,
                     __half* __restrict__ Ch, __half* __restrict__ Cl,
                     int M, int Nc, int K)
{
    extern __shared__ __half sm[];
    __half* As_hi = sm;                       // [2][A_SZ]
    __half* As_lo = As_hi + 2 * A_SZ;
    __half* Bs_hi = As_lo + 2 * A_SZ;         // [2][B_SZ]
    __half* Bs_lo = Bs_hi + 2 * B_SZ;

    const int tid  = threadIdx.x;
    const int lane = tid & 31;
    const int wid  = tid >> 5;             // 8 warps
    const int warp_m = (wid & 1) * 64;     // 2 warps in M
    const int warp_n = (wid >> 1) * 32;    // 4 warps in N
    const int rb = blockIdx.y * BM;
    const int cb = blockIdx.x * BN;
    const int nk = K / BK;

    // stage loader: pure 16B async copies
    auto load_stage = [&](int k0, int buf) {
        __half* ah = As_hi + buf * A_SZ;
        __half* al = As_lo + buf * A_SZ;
        __half* bh = Bs_hi + buf * B_SZ;
        __half* bl = Bs_lo + buf * B_SZ;
#pragma unroll
        for (int it = 0; it < 2; it++) {
            int c = tid + it * 256;            // A: 512 chunks of 8 halfs
            int row = c >> 2;
            int col = (c & 3) * 8;
            const __half* gsrc_h = &Ah[(size_t)(rb + row) * K + k0 + col];
            const __half* gsrc_l = &Al[(size_t)(rb + row) * K + k0 + col];
            cpa16(&ah[row * A_LD + col], gsrc_h);
            cpa16(&al[row * A_LD + col], gsrc_l);
        }
#pragma unroll
        for (int it = 0; it < 2; it++) {
            int c = tid + it * 256;            // B: 512 chunks of 8 halfs
            int row = c >> 4;
            int col = (c & 15) * 8;
            const __half* gsrc_h = &Bh[(size_t)(k0 + row) * Nc + cb + col];
            const __half* gsrc_l = &Bl[(size_t)(k0 + row) * Nc + cb + col];
            cpa16(&bh[row * B_LD + col], gsrc_h);
            cpa16(&bl[row * B_LD + col], gsrc_l);
        }
        asm volatile("cp.async.commit_group;" ::: "memory");
    };

    float acc[4][4][4] = {};               // 4 m16-tiles x 4 n8-tiles

    load_stage(0, 0);                      // prologue

    for (int kb = 0; kb < nk; kb++) {
        int buf = kb & 1;
        if (kb + 1 < nk) {
            load_stage((kb + 1) * BK, buf ^ 1);
            asm volatile("cp.async.wait_group 1;" ::: "memory");
        } else {
            asm volatile("cp.async.wait_group 0;" ::: "memory");
        }
        __syncthreads();

        const __half* ah = As_hi + buf * A_SZ;
        const __half* al = As_lo + buf * A_SZ;
        const __half* bh = Bs_hi + buf * B_SZ;
        const __half* bl = Bs_lo + buf * B_SZ;

#pragma unroll
        for (int kc = 0; kc < 2; kc++) {   // two k16 chunks per BK
            uint32_t af[4][4], bfh[2][4], bfl[2][4];
            const int a_row = lane & 15;
            const int a_col = kc * 16 + (lane >> 4) * 8;
            const int bg    = lane >> 3;   // 0..3
            const int b_k   = kc * 16 + (bg & 1) * 8 + (lane & 7);
#pragma unroll
            for (int j2 = 0; j2 < 2; j2++) {
                ldmBT(bfh[j2], &bh[b_k * B_LD + warp_n + j2 * 16 + (bg >> 1) * 8]);
                ldmBT(bfl[j2], &bl[b_k * B_LD + warp_n + j2 * 16 + (bg >> 1) * 8]);
            }
            // pass 1: hi(A) * hi(B)
#pragma unroll
            for (int i = 0; i < 4; i++)
                ldmA(af[i], &ah[(warp_m + i * 16 + a_row) * A_LD + a_col]);
#pragma unroll
            for (int i = 0; i < 4; i++)
#pragma unroll
                for (int j = 0; j < 4; j++)
                    mma16816(acc[i][j], af[i], &bfh[j >> 1][(j & 1) * 2]);
            // pass 2: hi(A) * lo(B)  (af reused)
#pragma unroll
            for (int i = 0; i < 4; i++)
#pragma unroll
                for (int j = 0; j < 4; j++)
                    mma16816(acc[i][j], af[i], &bfl[j >> 1][(j & 1) * 2]);
            // pass 3: lo(A) * hi(B)
#pragma unroll
            for (int i = 0; i < 4; i++)
                ldmA(af[i], &al[(warp_m + i * 16 + a_row) * A_LD + a_col]);
#pragma unroll
            for (int i = 0; i < 4; i++)
#pragma unroll
                for (int j = 0; j < 4; j++)
                    mma16816(acc[i][j], af[i], &bfh[j >> 1][(j & 1) * 2]);
        }
        __syncthreads();
    }

    // ---- epilogue: bias (+relu), fp32 or split-half stores ----
#pragma unroll
    for (int i = 0; i < 4; i++) {
        int r0 = rb + warp_m + i * 16 + (lane >> 2);
#pragma unroll
        for (int j = 0; j < 4; j++) {
            int c0 = cb + warp_n + j * 8 + (lane & 3) * 2;
            float bx = bias[c0], by = bias[c0 + 1];
#pragma unroll
            for (int half_ = 0; half_ < 2; half_++) {
                int r = r0 + half_ * 8;
                float vx = acc[i][j][half_ * 2 + 0] + bx;
                float vy = acc[i][j][half_ * 2 + 1] + by;
                if (RELU) { vx = fmaxf(vx, 0.f); vy = fmaxf(vy, 0.f); }
                if (SPLITOUT) {
                    __half2 hp = __floats2half2_rn(vx, vy);
                    float2 fp = __half22float2(hp);
                    __half2 lp = __floats2half2_rn(vx - fp.x, vy - fp.y);
                    *(__half2*)&Ch[(size_t)r * Nc + c0] = hp;
                    *(__half2*)&Cl[(size_t)r * Nc + c0] = lp;
                } else {
                    float2 o = {vx, vy};
                    *(float2*)&Cf[(size_t)r * Nc + c0] = o;
                }
            }
        }
    }
}

#define GEMM_SMEM (2 * (2 * A_SZ + 2 * B_SZ) * (int)sizeof(__half))

// ---------------- BatchNorm column stats (sum, sumsq) ----------------
#define BN_ROWS 128
__global__ void bn_stats_kernel(const float* __restrict__ X)
{
    int c = threadIdx.x;                  // 0..127
    size_t r0 = (size_t)blockIdx.x * BN_ROWS;
    float s = 0.f, ss = 0.f;
#pragma unroll 8
    for (int r = 0; r < BN_ROWS; r++) {
        float v = X[(r0 + r) * Dd + c];
        s += v;
        ss += v * v;
    }
    atomicAdd(&g_stats[c], s);
    atomicAdd(&g_stats[Dd + c], ss);
}

// ---------------- final BatchNorm normalize (no relu), layer 4 only ----------------
__global__ void bn_norm_kernel(const float* __restrict__ X, float* __restrict__ Y,
                               const float* __restrict__ gamma,
                               const float* __restrict__ beta)
{
    int idx = blockIdx.x * blockDim.x + threadIdx.x;
    int n = idx >> 5;
    int c = (idx & 31) * 4;
    const float inv_n = 1.0f / (float)Nn;
    float4 v = *(const float4*)&X[(size_t)n * Dd + c];
    float4 o;
#pragma unroll
    for (int t = 0; t < 4; t++) {
        int cc = c + t;
        float mu  = g_stats[cc] * inv_n;
        float var = g_stats[Dd + cc] * inv_n - mu * mu;
        float sc = rsqrtf(var + EPS) * gamma[cc];
        float sh = beta[cc] - mu * sc;
        ((float*)&o)[t] = ((const float*)&v)[t] * sc + sh;
    }
    *(float4*)&Y[(size_t)n * Dd + c] = o;
}

// ---------------- driver ----------------
extern "C" void kernel_launch(void* const* d_in, const int* in_sizes, int n_in,
                              void* d_out, int out_size)
{
    const int*   x          = (const int*)  d_in[0];
    const int*   edge_index = (const int*)  d_in[1];
    const int*   edge_attr  = (const int*)  d_in[2];
    const float* x_emb1     = (const float*)d_in[3];
    const float* x_emb2     = (const float*)d_in[4];
    const float* e_emb1     = (const float*)d_in[5];   // [5,6,128]
    const float* e_emb2     = (const float*)d_in[6];   // [5,3,128]
    const float* W1         = (const float*)d_in[7];   // [5,128,256]
    const float* b1         = (const float*)d_in[8];   // [5,256]
    const float* W2         = (const float*)d_in[9];   // [5,256,128]
    const float* b2         = (const float*)d_in[10];  // [5,128]
    const float* gamma      = (const float*)d_in[11];  // [5,128]
    const float* beta       = (const float*)d_in[12];  // [5,128]
    float* out = (float*)d_out;

    float *h, *agg, *stats;
    __half *aggh, *aggl, *hm1h, *hm1l, *w1h, *w1l, *w2h, *w2l;
    cudaGetSymbolAddress((void**)&h,     g_h);
    cudaGetSymbolAddress((void**)&agg,   g_agg);
    cudaGetSymbolAddress((void**)&aggh,  g_agg_hi);
    cudaGetSymbolAddress((void**)&aggl,  g_agg_lo);
    cudaGetSymbolAddress((void**)&hm1h,  g_hm1_hi);
    cudaGetSymbolAddress((void**)&hm1l,  g_hm1_lo);
    cudaGetSymbolAddress((void**)&w1h,   g_w1_hi);
    cudaGetSymbolAddress((void**)&w1l,   g_w1_lo);
    cudaGetSymbolAddress((void**)&w2h,   g_w2_hi);
    cudaGetSymbolAddress((void**)&w2l,   g_w2_lo);
    cudaGetSymbolAddress((void**)&stats, g_stats);

    cudaFuncSetAttribute(gemm_mma_kernel<true, true>,
                         cudaFuncAttributeMaxDynamicSharedMemorySize, GEMM_SMEM);
    cudaFuncSetAttribute(gemm_mma_kernel<false, false>,
                         cudaFuncAttributeMaxDynamicSharedMemorySize, GEMM_SMEM);

    split_weights_kernel<<<(5 * Dd * 2 * Dd) / 256, 256>>>(W1, W2);
    init_h_kernel<<<(Nn * 32) / 256, 256>>>(x, x_emb1, x_emb2, h);

    for (int l = 0; l < 5; l++) {
        const float* ee1 = e_emb1 + (size_t)l * 6 * Dd;
        const float* ee2 = e_emb2 + (size_t)l * 3 * Dd;
        const float* pg = gamma + (size_t)(l > 0 ? l - 1 : 0) * Dd;
        const float* pb = beta  + (size_t)(l > 0 ? l - 1 : 0) * Dd;
        int apply_bn = (l > 0) ? 1 : 0;

        agg_init_kernel<<<(Nn * 32) / 256, 256>>>(h, ee1, ee2, agg,
                                                  apply_bn, pg, pb);
        scatter_kernel<<<(Ee * 32) / 256, 256>>>(h, edge_index, edge_attr,
                                                 ee1, ee2, agg,
                                                 apply_bn, pg, pb);
        split_agg_kernel<<<(Nn * Dd / 4) / 256, 256>>>(agg, aggh, aggl);
        // hm1(hi,lo) = relu(agg @ W1[l] + b1[l])   [N,256]
        gemm_mma_kernel<true, true>
            <<<dim3(2 * Dd / BN, Nn / BM), 256, GEMM_SMEM>>>(
                aggh, aggl,
                w1h + (size_t)l * Dd * 2 * Dd, w1l + (size_t)l * Dd * 2 * Dd,
                b1 + (size_t)l * 2 * Dd,
                nullptr, hm1h, hm1l, Nn, 2 * Dd, Dd);
        // h(raw hm) = hm1 @ W2[l] + b2[l]   [N,128]
        gemm_mma_kernel<false, false>
            <<<dim3(Dd / BN, Nn / BM), 256, GEMM_SMEM>>>(
                hm1h, hm1l,
                w2h + (size_t)l * 2 * Dd * Dd, w2l + (size_t)l * 2 * Dd * Dd,
                b2 + (size_t)l * Dd,
                h, nullptr, nullptr, Nn, Dd, 2 * Dd);
        cudaMemsetAsync(stats, 0, 2 * Dd * sizeof(float), 0);
        bn_stats_kernel<<<Nn / BN_ROWS, Dd>>>(h);
        if (l == 4)
            bn_norm_kernel<<<(Nn * 32) / 256, 256>>>(h, out,
                                                     gamma + (size_t)4 * Dd,
                                                     beta + (size_t)4 * Dd);
    }
}